// round 2
// baseline (speedup 1.0000x reference)
#include <cuda_runtime.h>

// BilinearSampler: B=16, H=256, W=256, C=32, fp32, NHWC.
// out[b,h,w,c] = bilinear(img, x_s[b,h,w], y_s[b,h,w])[c]
//
// Strategy: 8 threads per output pixel; each thread handles a float4 (4
// channels). C = 32 floats = 128 bytes, so each 8-thread group issues one
// fully coalesced 128B load per corner and one 128B store. Memory-bound;
// rely on L2 to absorb the ~4x gather amplification (one batch image = 8 MB).

#define BS_B 16
#define BS_H 256
#define BS_W 256
#define BS_C 32          // floats per pixel
#define BS_C4 (BS_C / 4) // float4 per pixel = 8

__global__ __launch_bounds__(256) void bilinear_sampler_kernel(
    const float* __restrict__ img,   // [B,H,W,C]
    const float* __restrict__ xs,    // [B,H,W]
    const float* __restrict__ ys,    // [B,H,W]
    float* __restrict__ out)         // [B,H,W,C]
{
    // global thread id over B*H*W*8
    long long t = (long long)blockIdx.x * blockDim.x + threadIdx.x;
    const long long total = (long long)BS_B * BS_H * BS_W * BS_C4;
    if (t >= total) return;

    const int c4   = (int)(t & (BS_C4 - 1));   // which float4 within channel dim
    const long long pix = t >> 3;              // linear pixel index in [0, B*H*W)

    // Sample coords (broadcast load: 8 lanes read same address -> L1 broadcast)
    const float xsv = __ldg(&xs[pix]);
    const float ysv = __ldg(&ys[pix]);

    // Map [-1,1] -> [0, W-1] / [0, H-1]
    const float x = 0.5f * (xsv + 1.0f) * (float)(BS_W - 1);
    const float y = 0.5f * (ysv + 1.0f) * (float)(BS_H - 1);

    int x0 = (int)floorf(x);
    int y0 = (int)floorf(y);
    int x1 = x0 + 1;
    int y1 = y0 + 1;

    // clamp
    int x0c = min(max(x0, 0), BS_W - 1);
    int x1c = min(max(x1, 0), BS_W - 1);
    int y0c = min(max(y0, 0), BS_H - 1);
    int y1c = min(max(y1, 0), BS_H - 1);

    // weights from CLAMPED coords (matches reference exactly)
    const float x0f = (float)x0c, x1f = (float)x1c;
    const float y0f = (float)y0c, y1f = (float)y1c;
    const float wa = (x1f - x) * (y1f - y);   // (y0c, x0c)
    const float wb = (x1f - x) * (y - y0f);   // (y1c, x0c)
    const float wc = (x - x0f) * (y1f - y);   // (y0c, x1c)
    const float wd = (x - x0f) * (y - y0f);   // (y1c, x1c)

    // batch base: pix = ((b*H + h)*W + w); batch index = pix / (H*W)
    const long long b   = pix >> 16;                 // H*W = 65536
    const long long bimg = b * (long long)(BS_H * BS_W * BS_C);

    const int co = c4 * 4;
    const float4* pa = (const float4*)&img[bimg + ((long long)y0c * BS_W + x0c) * BS_C + co];
    const float4* pb = (const float4*)&img[bimg + ((long long)y1c * BS_W + x0c) * BS_C + co];
    const float4* pc = (const float4*)&img[bimg + ((long long)y0c * BS_W + x1c) * BS_C + co];
    const float4* pd = (const float4*)&img[bimg + ((long long)y1c * BS_W + x1c) * BS_C + co];

    const float4 Ia = __ldg(pa);
    const float4 Ib = __ldg(pb);
    const float4 Ic = __ldg(pc);
    const float4 Id = __ldg(pd);

    float4 r;
    r.x = wa * Ia.x + wb * Ib.x + wc * Ic.x + wd * Id.x;
    r.y = wa * Ia.y + wb * Ib.y + wc * Ic.y + wd * Id.y;
    r.z = wa * Ia.z + wb * Ib.z + wc * Ic.z + wd * Id.z;
    r.w = wa * Ia.w + wb * Ib.w + wc * Ic.w + wd * Id.w;

    ((float4*)&out[pix * BS_C + co])[0] = r;
}

extern "C" void kernel_launch(void* const* d_in, const int* in_sizes, int n_in,
                              void* d_out, int out_size) {
    const float* img = (const float*)d_in[0];
    const float* xs  = (const float*)d_in[1];
    const float* ys  = (const float*)d_in[2];
    float* out = (float*)d_out;

    const long long total = (long long)BS_B * BS_H * BS_W * BS_C4; // 8.4M threads
    const int threads = 256;
    const int blocks = (int)((total + threads - 1) / threads);
    bilinear_sampler_kernel<<<blocks, threads>>>(img, xs, ys, out);
}

// round 3
// speedup vs baseline: 1.1295x; 1.1295x over previous
#include <cuda_runtime.h>

// BilinearSampler: B=16, H=256, W=256, C=32, fp32, NHWC.
//
// R2: latency-bound fix. 8 threads per pixel (one float4 each, fully
// coalesced 128B per corner), but each thread now processes TWO pixels
// (e and e + total/2) so 8 independent corner gathers are in flight at
// once instead of 4. Output uses streaming stores (__stcs) so the
// write-once output stream doesn't evict the gather-reused image lines
// from L2.

#define BS_B 16
#define BS_H 256
#define BS_W 256
#define BS_C 32          // floats per pixel
#define BS_C4 (BS_C / 4) // float4 per pixel = 8

struct Corner4 {
    const float4* pa; const float4* pb; const float4* pc; const float4* pd;
    float wa, wb, wc, wd;
};

__device__ __forceinline__ Corner4 make_corners(const float* __restrict__ img,
                                                float xsv, float ysv,
                                                long long pix, int co)
{
    const float x = 0.5f * (xsv + 1.0f) * (float)(BS_W - 1);
    const float y = 0.5f * (ysv + 1.0f) * (float)(BS_H - 1);

    int x0 = __float2int_rd(x);
    int y0 = __float2int_rd(y);
    int x1 = x0 + 1;
    int y1 = y0 + 1;

    int x0c = min(max(x0, 0), BS_W - 1);
    int x1c = min(max(x1, 0), BS_W - 1);
    int y0c = min(max(y0, 0), BS_H - 1);
    int y1c = min(max(y1, 0), BS_H - 1);

    const float x0f = (float)x0c, x1f = (float)x1c;
    const float y0f = (float)y0c, y1f = (float)y1c;

    Corner4 r;
    r.wa = (x1f - x) * (y1f - y);
    r.wb = (x1f - x) * (y - y0f);
    r.wc = (x - x0f) * (y1f - y);
    r.wd = (x - x0f) * (y - y0f);

    const long long b    = pix >> 16;   // H*W = 65536
    const long long bimg = b * (long long)(BS_H * BS_W * BS_C);

    r.pa = (const float4*)&img[bimg + ((long long)y0c * BS_W + x0c) * BS_C + co];
    r.pb = (const float4*)&img[bimg + ((long long)y1c * BS_W + x0c) * BS_C + co];
    r.pc = (const float4*)&img[bimg + ((long long)y0c * BS_W + x1c) * BS_C + co];
    r.pd = (const float4*)&img[bimg + ((long long)y1c * BS_W + x1c) * BS_C + co];
    return r;
}

__device__ __forceinline__ float4 blend(const float4 Ia, const float4 Ib,
                                        const float4 Ic, const float4 Id,
                                        float wa, float wb, float wc, float wd)
{
    float4 r;
    r.x = wa * Ia.x + wb * Ib.x + wc * Ic.x + wd * Id.x;
    r.y = wa * Ia.y + wb * Ib.y + wc * Ic.y + wd * Id.y;
    r.z = wa * Ia.z + wb * Ib.z + wc * Ic.z + wd * Id.z;
    r.w = wa * Ia.w + wb * Ib.w + wc * Ic.w + wd * Id.w;
    return r;
}

__global__ __launch_bounds__(256) void bilinear_sampler_kernel(
    const float* __restrict__ img,   // [B,H,W,C]
    const float* __restrict__ xs,    // [B,H,W]
    const float* __restrict__ ys,    // [B,H,W]
    float* __restrict__ out)         // [B,H,W,C]
{
    const long long total = (long long)BS_B * BS_H * BS_W * BS_C4; // 16.8M elems /2
    const long long half  = total >> 1;

    long long t = (long long)blockIdx.x * blockDim.x + threadIdx.x;
    if (t >= half) return;

    const long long e0 = t;
    const long long e1 = t + half;

    const int       c4   = (int)(e0 & (BS_C4 - 1));
    const int       co   = c4 * 4;
    const long long pix0 = e0 >> 3;
    const long long pix1 = e1 >> 3;   // = pix0 + B*H*W/2

    // Issue both pixels' coord loads together (4 independent loads in flight).
    const float xs0 = __ldg(&xs[pix0]);
    const float ys0 = __ldg(&ys[pix0]);
    const float xs1 = __ldg(&xs[pix1]);
    const float ys1 = __ldg(&ys[pix1]);

    // Address/weight math for both pixels.
    Corner4 k0 = make_corners(img, xs0, ys0, pix0, co);
    Corner4 k1 = make_corners(img, xs1, ys1, pix1, co);

    // Issue all 8 corner gathers before consuming any (MLP = 8).
    const float4 a0 = __ldg(k0.pa);
    const float4 b0 = __ldg(k0.pb);
    const float4 c0 = __ldg(k0.pc);
    const float4 d0 = __ldg(k0.pd);
    const float4 a1 = __ldg(k1.pa);
    const float4 b1 = __ldg(k1.pb);
    const float4 c1 = __ldg(k1.pc);
    const float4 d1 = __ldg(k1.pd);

    const float4 r0 = blend(a0, b0, c0, d0, k0.wa, k0.wb, k0.wc, k0.wd);
    const float4 r1 = blend(a1, b1, c1, d1, k1.wa, k1.wb, k1.wc, k1.wd);

    // Streaming stores: output is write-once; keep img resident in L2.
    __stcs((float4*)&out[pix0 * BS_C + co], r0);
    __stcs((float4*)&out[pix1 * BS_C + co], r1);
}

extern "C" void kernel_launch(void* const* d_in, const int* in_sizes, int n_in,
                              void* d_out, int out_size) {
    const float* img = (const float*)d_in[0];
    const float* xs  = (const float*)d_in[1];
    const float* ys  = (const float*)d_in[2];
    float* out = (float*)d_out;

    const long long total = (long long)BS_B * BS_H * BS_W * BS_C4;
    const long long half  = total >> 1;
    const int threads = 256;
    const int blocks = (int)((half + threads - 1) / threads);
    bilinear_sampler_kernel<<<blocks, threads>>>(img, xs, ys, out);
}